// round 5
// baseline (speedup 1.0000x reference)
#include <cuda_runtime.h>
#include <cstdint>

// POLLU RHS: dy[b][s] = sum_r S[s][r]*k[r]*C[a_r][b]*C[b_r][b]
// Input  conc: [20, B] species-major -> coalesced LDG with L2 evict_last
//              fractional policy (persist ~60% of input across graph replays;
//              fractional marking defeats cyclic-thrash on a 160MB stream vs 126MB L2).
// Output dy  : [B, 20] batch-major -> per-warp smem staging + per-warp TMA bulk
//              store with L2 evict_first (don't displace the persistent input set).

#define TILE 256   // 8 warps/block, 1 column/thread

__device__ __forceinline__ float ldg_keep(const float* p, uint64_t pol) {
    float v;
    asm volatile("ld.global.nc.L2::cache_hint.f32 %0, [%1], %2;"
                 : "=f"(v) : "l"(p), "l"(pol));
    return v;
}

__global__ __launch_bounds__(TILE)
void pollu_kernel(const float* __restrict__ conc,
                  const float* __restrict__ k,
                  float* __restrict__ out,
                  int B)
{
    __shared__ __align__(16) float s_dy[TILE * 20];   // 20 KB; warp w owns [w*640, w*640+640)

    const int tid  = threadIdx.x;
    const int wid  = tid >> 5;
    const int lane = tid & 31;
    const int b0   = blockIdx.x * TILE;
    const int b    = b0 + tid;

    const int warp_b0    = b0 + wid * 32;
    const int warp_valid = min(32, B - warp_b0);

    // L2 policies: input persists (60% evict_last, rest streams out fast),
    // output streams (evict_first).
    uint64_t pol_in, pol_out;
    asm("createpolicy.fractional.L2::evict_last.L2::evict_first.b64 %0, 0.6;"
        : "=l"(pol_in));
    asm("createpolicy.fractional.L2::evict_first.b64 %0, 1.0;"
        : "=l"(pol_out));

    if (b < B) {
        // ---- coalesced loads: 20 species rows, stride B ----
        float C0  = ldg_keep(&conc[ 0*B + b], pol_in);
        float C1  = ldg_keep(&conc[ 1*B + b], pol_in);
        float C2  = ldg_keep(&conc[ 2*B + b], pol_in);
        float C3  = ldg_keep(&conc[ 3*B + b], pol_in);
        float C4  = ldg_keep(&conc[ 4*B + b], pol_in);
        float C5  = ldg_keep(&conc[ 5*B + b], pol_in);
        float C6  = ldg_keep(&conc[ 6*B + b], pol_in);
        float C8  = ldg_keep(&conc[ 8*B + b], pol_in);
        float C9  = ldg_keep(&conc[ 9*B + b], pol_in);
        float C10 = ldg_keep(&conc[10*B + b], pol_in);
        float C12 = ldg_keep(&conc[12*B + b], pol_in);
        float C13 = ldg_keep(&conc[13*B + b], pol_in);
        float C15 = ldg_keep(&conc[15*B + b], pol_in);
        float C16 = ldg_keep(&conc[16*B + b], pol_in);
        float C18 = ldg_keep(&conc[18*B + b], pol_in);
        float C19 = ldg_keep(&conc[19*B + b], pol_in);

        // ---- 25 fluxes (k loads broadcast, L1-resident) ----
        float r1  = __ldg(&k[ 0]) * C0;
        float r2  = __ldg(&k[ 1]) * C1  * C3;
        float r3  = __ldg(&k[ 2]) * C4  * C1;
        float r4  = __ldg(&k[ 3]) * C6;
        float r5  = __ldg(&k[ 4]) * C6;
        float r6  = __ldg(&k[ 5]) * C6  * C5;
        float r7  = __ldg(&k[ 6]) * C8;
        float r8  = __ldg(&k[ 7]) * C8  * C5;
        float r9  = __ldg(&k[ 8]) * C10 * C1;
        float r10 = __ldg(&k[ 9]) * C10 * C0;
        float r11 = __ldg(&k[10]) * C12;
        float r12 = __ldg(&k[11]) * C9  * C1;
        float r13 = __ldg(&k[12]) * C13;
        float r14 = __ldg(&k[13]) * C0  * C5;
        float r15 = __ldg(&k[14]) * C2;
        float r16 = __ldg(&k[15]) * C3;
        float r17 = __ldg(&k[16]) * C3;
        float r18 = __ldg(&k[17]) * C15;
        float r19 = __ldg(&k[18]) * C15;
        float r20 = __ldg(&k[19]) * C16 * C5;
        float r21 = __ldg(&k[20]) * C18;
        float r22 = __ldg(&k[21]) * C18;
        float r23 = __ldg(&k[22]) * C0  * C3;
        float r24 = __ldg(&k[23]) * C18 * C0;
        float r25 = __ldg(&k[24]) * C19;

        // ---- stoichiometry ----
        float d0  = -r1 - r10 - r14 - r23 - r24 + r2 + r3 + r9 + r11 + r12 + r22 + r25;
        float d1  = -r2 - r3 - r9 - r12 + r1 + r21;
        float d2  = -r15 + r1 + r17 + r19 + r22;
        float d3  = -r2 - r16 - r17 - r23 + r15;
        float d4  = -r3 + 2.0f*r4 + r6 + r7 + r13 + r20;
        float d5  = -r6 - r8 - r14 - r20 + r3 + 2.0f*r18;
        float d6  = -r4 - r5 - r6 + r13;
        float d7  =  r4 + r5 + r6 + r7;
        float d8  = -r7 - r8;
        float d9  = -r12 + r7 + r9;
        float d10 = -r9 - r10 + r8 + r11;
        float d11 =  r9;
        float d12 = -r11 + r10;
        float d13 = -r13 + r12;
        float d14 =  r14;
        float d15 = -r18 - r19 + r16;
        float d16 = -r20;
        float d17 =  r20;
        float d18 = -r21 - r22 - r24 + r23 + r25;
        float d19 = -r25 + r24;

        // ---- 5x STS.128, conflict-free in unpadded [TILE][20] ----
        float4* srow = reinterpret_cast<float4*>(&s_dy[tid * 20]);
        srow[0] = make_float4(d0,  d1,  d2,  d3);
        srow[1] = make_float4(d4,  d5,  d6,  d7);
        srow[2] = make_float4(d8,  d9,  d10, d11);
        srow[3] = make_float4(d12, d13, d14, d15);
        srow[4] = make_float4(d16, d17, d18, d19);
    }

    // ---- per-warp drain (no block barriers) ----
    __syncwarp();
    if (warp_valid > 0) {
        asm volatile("fence.proxy.async.shared::cta;" ::: "memory");
        if (lane == 0) {
            uint32_t smem_addr;
            asm("{ .reg .u64 t; cvta.to.shared.u64 t, %1; cvt.u32.u64 %0, t; }"
                : "=r"(smem_addr) : "l"(&s_dy[wid * 32 * 20]));

            float*   gdst  = out + (long long)warp_b0 * 20;                // 2560B-aligned
            unsigned bytes = (unsigned)(warp_valid * 20 * sizeof(float));  // mult of 16

            asm volatile(
                "cp.async.bulk.global.shared::cta.bulk_group.L2::cache_hint "
                "[%0], [%1], %2, %3;"
                :: "l"(gdst), "r"(smem_addr), "r"(bytes), "l"(pol_out)
                : "memory");
            asm volatile("cp.async.bulk.commit_group;" ::: "memory");
            asm volatile("cp.async.bulk.wait_group 0;" ::: "memory");
        }
    }
}

extern "C" void kernel_launch(void* const* d_in, const int* in_sizes, int n_in,
                              void* d_out, int out_size)
{
    // inputs per metadata order: t [1], conc_in [20*B], k [25]
    const float* conc = (const float*)d_in[1];
    const float* k    = (const float*)d_in[2];
    float* out        = (float*)d_out;
    const int B = in_sizes[1] / 20;

    const int grid = (B + TILE - 1) / TILE;
    pollu_kernel<<<grid, TILE>>>(conc, k, out, B);
}

// round 6
// speedup vs baseline: 1.0746x; 1.0746x over previous
#include <cuda_runtime.h>
#include <cstdint>

// POLLU RHS: dy[b][s] = sum_r S[s][r]*k[r]*C[a_r][b]*C[b_r][b]
// Input  conc: [20, B] species-major. The 16 used species rows of each 256-col
//   tile are fetched by 16x 1KB cp.async.bulk (TMA) copies into smem, signaled
//   via one mbarrier (expect_tx). Warps sleep on try_wait instead of burning
//   scoreboard slots on 16 scalar LDGs -> deep, scheduler-independent MLP.
// Output dy  : [B, 20] batch-major -> unpadded smem staging (conflict-free
//   5x STS.128) drained by per-warp cp.async.bulk stores (R4-proven path).

#define TILE 256
#define NSP  16    // species used as reactants (7,11,14,17 never read)

__device__ __forceinline__ uint32_t s2u(const void* p) {
    uint32_t a;
    asm("{ .reg .u64 t; cvta.to.shared.u64 t, %1; cvt.u32.u64 %0, t; }"
        : "=r"(a) : "l"(p));
    return a;
}

__global__ __launch_bounds__(TILE)
void pollu_kernel(const float* __restrict__ conc,
                  const float* __restrict__ k,
                  float* __restrict__ out,
                  int B)
{
    __shared__ __align__(16) float s_in[NSP * TILE];   // 16 KB
    __shared__ __align__(16) float s_out[TILE * 20];   // 20 KB
    __shared__ __align__(8)  uint64_t mbar;

    const int tid  = threadIdx.x;
    const int wid  = tid >> 5;
    const int lane = tid & 31;
    const int b0   = blockIdx.x * TILE;
    const int b    = b0 + tid;
    const int n_valid = min(TILE, B - b0);

    // TMA path needs 16B-aligned addresses+sizes: row starts at conc + sp*B + b0
    // (b0 mult of 256) -> need (B*4)%16==0 and (n_valid*4)%16==0. Uniform per block.
    const bool use_tma = ((B & 3) == 0) && ((n_valid & 3) == 0);

    float C0, C1, C2, C3, C4, C5, C6, C8, C9, C10, C12, C13, C15, C16, C18, C19;

    if (use_tma) {
        if (tid == 0) {
            asm volatile("mbarrier.init.shared.b64 [%0], 1;"
                         :: "r"(s2u(&mbar)) : "memory");
        }
        __syncthreads();   // publish mbarrier init before anyone waits

        if (tid == 0) {
            const unsigned row_bytes = (unsigned)(n_valid * 4);
            asm volatile("mbarrier.arrive.expect_tx.shared.b64 _, [%0], %1;"
                         :: "r"(s2u(&mbar)), "r"(row_bytes * NSP) : "memory");
            const int sp[NSP] = {0,1,2,3,4,5,6,8,9,10,12,13,15,16,18,19};
            #pragma unroll
            for (int i = 0; i < NSP; i++) {
                const float* gsrc = conc + (long long)sp[i] * B + b0;
                asm volatile(
                    "cp.async.bulk.shared::cta.global.mbarrier::complete_tx::bytes "
                    "[%0], [%1], %2, [%3];"
                    :: "r"(s2u(&s_in[i * TILE])), "l"(gsrc),
                       "r"(row_bytes), "r"(s2u(&mbar))
                    : "memory");
            }
        }

        // all threads: sleep-wait for the whole 16KB tile (phase parity 0)
        {
            uint32_t mb = s2u(&mbar);
            asm volatile(
                "{\n\t.reg .pred P;\n\t"
                "WAIT_%=:\n\t"
                "mbarrier.try_wait.parity.acquire.cta.shared::cta.b64 P, [%0], 0, 0x989680;\n\t"
                "@P bra.uni DONE_%=;\n\t"
                "bra.uni WAIT_%=;\n\t"
                "DONE_%=:\n\t}"
                :: "r"(mb) : "memory");
        }

        // conflict-free LDS: lane l reads consecutive word l within each row
        C0  = s_in[ 0*TILE + tid];  C1  = s_in[ 1*TILE + tid];
        C2  = s_in[ 2*TILE + tid];  C3  = s_in[ 3*TILE + tid];
        C4  = s_in[ 4*TILE + tid];  C5  = s_in[ 5*TILE + tid];
        C6  = s_in[ 6*TILE + tid];  C8  = s_in[ 7*TILE + tid];
        C9  = s_in[ 8*TILE + tid];  C10 = s_in[ 9*TILE + tid];
        C12 = s_in[10*TILE + tid];  C13 = s_in[11*TILE + tid];
        C15 = s_in[12*TILE + tid];  C16 = s_in[13*TILE + tid];
        C18 = s_in[14*TILE + tid];  C19 = s_in[15*TILE + tid];
    } else {
        // fallback (tail/misaligned blocks): direct coalesced LDG
        if (b < B) {
            C0  = __ldg(&conc[ 0*B + b]);  C1  = __ldg(&conc[ 1*B + b]);
            C2  = __ldg(&conc[ 2*B + b]);  C3  = __ldg(&conc[ 3*B + b]);
            C4  = __ldg(&conc[ 4*B + b]);  C5  = __ldg(&conc[ 5*B + b]);
            C6  = __ldg(&conc[ 6*B + b]);  C8  = __ldg(&conc[ 8*B + b]);
            C9  = __ldg(&conc[ 9*B + b]);  C10 = __ldg(&conc[10*B + b]);
            C12 = __ldg(&conc[12*B + b]);  C13 = __ldg(&conc[13*B + b]);
            C15 = __ldg(&conc[15*B + b]);  C16 = __ldg(&conc[16*B + b]);
            C18 = __ldg(&conc[18*B + b]);  C19 = __ldg(&conc[19*B + b]);
        }
    }

    if (b < B) {
        // ---- 25 fluxes (k loads broadcast, L1-resident) ----
        float r1  = __ldg(&k[ 0]) * C0;
        float r2  = __ldg(&k[ 1]) * C1  * C3;
        float r3  = __ldg(&k[ 2]) * C4  * C1;
        float r4  = __ldg(&k[ 3]) * C6;
        float r5  = __ldg(&k[ 4]) * C6;
        float r6  = __ldg(&k[ 5]) * C6  * C5;
        float r7  = __ldg(&k[ 6]) * C8;
        float r8  = __ldg(&k[ 7]) * C8  * C5;
        float r9  = __ldg(&k[ 8]) * C10 * C1;
        float r10 = __ldg(&k[ 9]) * C10 * C0;
        float r11 = __ldg(&k[10]) * C12;
        float r12 = __ldg(&k[11]) * C9  * C1;
        float r13 = __ldg(&k[12]) * C13;
        float r14 = __ldg(&k[13]) * C0  * C5;
        float r15 = __ldg(&k[14]) * C2;
        float r16 = __ldg(&k[15]) * C3;
        float r17 = __ldg(&k[16]) * C3;
        float r18 = __ldg(&k[17]) * C15;
        float r19 = __ldg(&k[18]) * C15;
        float r20 = __ldg(&k[19]) * C16 * C5;
        float r21 = __ldg(&k[20]) * C18;
        float r22 = __ldg(&k[21]) * C18;
        float r23 = __ldg(&k[22]) * C0  * C3;
        float r24 = __ldg(&k[23]) * C18 * C0;
        float r25 = __ldg(&k[24]) * C19;

        // ---- stoichiometry ----
        float d0  = -r1 - r10 - r14 - r23 - r24 + r2 + r3 + r9 + r11 + r12 + r22 + r25;
        float d1  = -r2 - r3 - r9 - r12 + r1 + r21;
        float d2  = -r15 + r1 + r17 + r19 + r22;
        float d3  = -r2 - r16 - r17 - r23 + r15;
        float d4  = -r3 + 2.0f*r4 + r6 + r7 + r13 + r20;
        float d5  = -r6 - r8 - r14 - r20 + r3 + 2.0f*r18;
        float d6  = -r4 - r5 - r6 + r13;
        float d7  =  r4 + r5 + r6 + r7;
        float d8  = -r7 - r8;
        float d9  = -r12 + r7 + r9;
        float d10 = -r9 - r10 + r8 + r11;
        float d11 =  r9;
        float d12 = -r11 + r10;
        float d13 = -r13 + r12;
        float d14 =  r14;
        float d15 = -r18 - r19 + r16;
        float d16 = -r20;
        float d17 =  r20;
        float d18 = -r21 - r22 - r24 + r23 + r25;
        float d19 = -r25 + r24;

        // ---- 5x STS.128, conflict-free in unpadded [TILE][20] layout ----
        float4* srow = reinterpret_cast<float4*>(&s_out[tid * 20]);
        srow[0] = make_float4(d0,  d1,  d2,  d3);
        srow[1] = make_float4(d4,  d5,  d6,  d7);
        srow[2] = make_float4(d8,  d9,  d10, d11);
        srow[3] = make_float4(d12, d13, d14, d15);
        srow[4] = make_float4(d16, d17, d18, d19);
    }

    // ---- per-warp drain (no block barriers) ----
    const int warp_b0    = b0 + wid * 32;
    const int warp_valid = min(32, B - warp_b0);
    __syncwarp();
    if (warp_valid > 0) {
        asm volatile("fence.proxy.async.shared::cta;" ::: "memory");
        if (lane == 0) {
            float*   gdst  = out + (long long)warp_b0 * 20;               // 2560B-aligned
            unsigned bytes = (unsigned)(warp_valid * 20 * sizeof(float)); // mult of 16

            asm volatile(
                "cp.async.bulk.global.shared::cta.bulk_group [%0], [%1], %2;"
                :: "l"(gdst), "r"(s2u(&s_out[wid * 32 * 20])), "r"(bytes)
                : "memory");
            asm volatile("cp.async.bulk.commit_group;" ::: "memory");
            asm volatile("cp.async.bulk.wait_group 0;" ::: "memory");
        }
    }
}

extern "C" void kernel_launch(void* const* d_in, const int* in_sizes, int n_in,
                              void* d_out, int out_size)
{
    // inputs per metadata order: t [1], conc_in [20*B], k [25]
    const float* conc = (const float*)d_in[1];
    const float* k    = (const float*)d_in[2];
    float* out        = (float*)d_out;
    const int B = in_sizes[1] / 20;

    const int grid = (B + TILE - 1) / TILE;
    pollu_kernel<<<grid, TILE>>>(conc, k, out, B);
}